// round 3
// baseline (speedup 1.0000x reference)
#include <cuda_runtime.h>
#include <cuda_fp16.h>
#include <cstdint>
#include <math.h>

// ---------------------------------------------------------------------------
// Problem constants
// ---------------------------------------------------------------------------
#define BS   2
#define NQ   16384
#define E    256
#define NH   8
#define NL   4
#define NP   4
#define TOTV 21760         // total spatial positions across levels
#define NOUT 384           // 256 offsets + 128 attn logits per query
#define M_TOT (BS * NQ)    // 32768
#define GEMM_BLOCKS 768    // 256 m-tiles * 3 n-tiles
#define CONV_BLOCKS 21760  // BS*TOTV*NH*16 half2 / 256 threads

// Scratch for GEMM output: [32768, 384] f32
__device__ float g_scratch[(size_t)M_TOT * NOUT];
// fp16 value cache, transposed: [b][h][pos][32ch]
__device__ __align__(128) __half g_vcache[(size_t)BS * NH * TOTV * 32];

// ---------------------------------------------------------------------------
// tf32 mma (operands raw fp32 bits -> hw truncates to tf32)
// ---------------------------------------------------------------------------
__device__ __forceinline__ void mma_tf32(float c[4], const unsigned a[4],
                                         unsigned b0, unsigned b1) {
    asm volatile(
        "mma.sync.aligned.m16n8k8.row.col.f32.tf32.tf32.f32 "
        "{%0,%1,%2,%3}, {%4,%5,%6,%7}, {%8,%9}, {%0,%1,%2,%3};"
        : "+f"(c[0]), "+f"(c[1]), "+f"(c[2]), "+f"(c[3])
        : "r"(a[0]), "r"(a[1]), "r"(a[2]), "r"(a[3]), "r"(b0), "r"(b1));
}

// ---------------------------------------------------------------------------
// Fused kernel: blocks [0, GEMM_BLOCKS) run the projection GEMM,
// blocks [GEMM_BLOCKS, GEMM_BLOCKS+CONV_BLOCKS) convert value -> fp16
// transposed cache. Independent work; co-scheduled in one launch.
// ---------------------------------------------------------------------------
__global__ __launch_bounds__(256) void gemm_conv_kernel(
    const float* __restrict__ Q,
    const float* __restrict__ value,
    const float* __restrict__ Woff,
    const float* __restrict__ Wattn,
    const float* __restrict__ boff,
    const float* __restrict__ battn)
{
    if (blockIdx.x >= GEMM_BLOCKS) {
        // ---- value -> fp16 transposed cache ----
        // t indexes half2 pairs: c2 (0..15) | h (0..7) | pos | b
        int t = (blockIdx.x - GEMM_BLOCKS) * 256 + threadIdx.x;
        int c2 = t & 15;
        int h  = (t >> 4) & 7;
        int pb = t >> 7;                // b*TOTV + pos
        int pos = pb % TOTV;
        int b   = pb / TOTV;
        float2 v = *(const float2*)(value +
            (((size_t)pb * NH + h) * 32 + 2 * c2));
        ((__half2*)g_vcache)[((size_t)(b * NH + h) * TOTV + pos) * 16 + c2] =
            __float22half2_rn(v);
        return;
    }

    // ---- GEMM: C[m,n] = sum_k Q[m,k]*Wc[n,k] + bias[n] ----
    __shared__ float As[128][36];
    __shared__ float Bs[128][36];

    const int tid  = threadIdx.x;
    const int mblk = blockIdx.x & 255;
    const int nblk = blockIdx.x >> 8;
    const int m0   = mblk * 128;
    const int n0   = nblk * 128;
    const int warp = tid >> 5, lane = tid & 31;
    const int wm   = (warp & 3) * 32;
    const int wn   = (warp >> 2) * 64;
    const int g    = lane >> 2;
    const int tg   = lane & 3;

    const float* Bbase = (nblk == 2) ? Wattn : (Woff + (size_t)n0 * 256);

    float acc[2][8][4];
#pragma unroll
    for (int mi = 0; mi < 2; mi++)
#pragma unroll
        for (int ni = 0; ni < 8; ni++)
#pragma unroll
            for (int k = 0; k < 4; k++) acc[mi][ni][k] = 0.f;

    float4 aS[4], bS[4];
#pragma unroll
    for (int i = 0; i < 4; i++) {
        int idx = tid + i * 256;
        int r = idx >> 3, c = (idx & 7) * 4;
        aS[i] = *(const float4*)(Q + (size_t)(m0 + r) * 256 + c);
        bS[i] = *(const float4*)(Bbase + (size_t)r * 256 + c);
    }

#pragma unroll
    for (int kt = 0; kt < 8; kt++) {
        if (kt) __syncthreads();
#pragma unroll
        for (int i = 0; i < 4; i++) {
            int idx = tid + i * 256;
            int r = idx >> 3, c = (idx & 7) * 4;
            *(float4*)(&As[r][c]) = aS[i];
            *(float4*)(&Bs[r][c]) = bS[i];
        }
        __syncthreads();
        if (kt < 7) {
            int koff = (kt + 1) * 32;
#pragma unroll
            for (int i = 0; i < 4; i++) {
                int idx = tid + i * 256;
                int r = idx >> 3, c = (idx & 7) * 4;
                aS[i] = *(const float4*)(Q + (size_t)(m0 + r) * 256 + koff + c);
                bS[i] = *(const float4*)(Bbase + (size_t)r * 256 + koff + c);
            }
        }
#pragma unroll
        for (int kk = 0; kk < 32; kk += 8) {
            unsigned a[2][4];
#pragma unroll
            for (int mi = 0; mi < 2; mi++) {
                int r = wm + mi * 16 + g;
                a[mi][0] = __float_as_uint(As[r][kk + tg]);
                a[mi][1] = __float_as_uint(As[r + 8][kk + tg]);
                a[mi][2] = __float_as_uint(As[r][kk + tg + 4]);
                a[mi][3] = __float_as_uint(As[r + 8][kk + tg + 4]);
            }
#pragma unroll
            for (int ni = 0; ni < 8; ni++) {
                unsigned b0 = __float_as_uint(Bs[wn + ni * 8 + g][kk + tg]);
                unsigned b1 = __float_as_uint(Bs[wn + ni * 8 + g][kk + tg + 4]);
                mma_tf32(acc[0][ni], a[0], b0, b1);
                mma_tf32(acc[1][ni], a[1], b0, b1);
            }
        }
    }

#pragma unroll
    for (int mi = 0; mi < 2; mi++) {
        int row = m0 + wm + mi * 16 + g;
#pragma unroll
        for (int ni = 0; ni < 8; ni++) {
            int col = n0 + wn + ni * 8 + 2 * tg;
            float b0v = (col < 256) ? boff[col] : battn[col - 256];
            float b1v = (col + 1 < 256) ? boff[col + 1] : battn[col + 1 - 256];
            g_scratch[(size_t)row * NOUT + col]           = acc[mi][ni][0] + b0v;
            g_scratch[(size_t)row * NOUT + col + 1]       = acc[mi][ni][1] + b1v;
            g_scratch[(size_t)(row + 8) * NOUT + col]     = acc[mi][ni][2] + b0v;
            g_scratch[(size_t)(row + 8) * NOUT + col + 1] = acc[mi][ni][3] + b1v;
        }
    }
}

// ---------------------------------------------------------------------------
// MSDA kernel: softmax + 16-point bilinear gather + weighted sum.
// One warp per query. fp16 cache layout [b][h][pos][32ch]: the two x-columns
// of a tap are adjacent positions -> one full-warp LDG.32 covers both columns
// of one row as a single 128B contiguous request (lane = half*16 + chpair;
// colB offset == the half*16 half2 offset). Validity+bilinear+softmax weights
// folded per precompute lane; hot loop: 3 SHFL + 2 LDG + 4 CVT + 4 FFMA.
// ---------------------------------------------------------------------------
__global__ __launch_bounds__(1024) void msda_kernel(
    const float* __restrict__ refp,
    float* __restrict__ out)
{
    const int b    = blockIdx.z;
    const int h    = blockIdx.y;
    const int warp = threadIdx.x >> 5;
    const int lane = threadIdx.x & 31;
    const int q    = blockIdx.x * 32 + warp;
    const int qg   = b * NQ + q;

    const float* sc = g_scratch + (size_t)qg * NOUT;

    const int pt   = lane & 15;       // point index (precompute in both halves)
    const int half = lane >> 4;       // 0 -> colA (x0), 1 -> colB (x1)
    const int l    = pt >> 2;
    const int p    = pt & 3;
    const int Wl   = 128 >> l;
    const int start = (l == 0) ? 0 : (l == 1) ? 16384 : (l == 2) ? 20480 : 21504;

    // ---- softmax over the 16 logits (replicated in both halves) ----
    float lg = sc[256 + h * 16 + pt];
    float mx = lg;
#pragma unroll
    for (int o = 8; o; o >>= 1)
        mx = fmaxf(mx, __shfl_xor_sync(0xffffffffu, mx, o));
    float e = __expf(lg - mx);
    float s = e;
#pragma unroll
    for (int o = 8; o; o >>= 1)
        s += __shfl_xor_sync(0xffffffffu, s, o);
    float w = e / s;

    // ---- per-point sampling position, clamped base + folded weights ----
    float2 of = ((const float2*)(sc + h * 32))[pt];
    float2 rp = ((const float2*)(refp + (size_t)qg * 8))[p];

    float x = rp.x * (float)Wl + of.x - 0.5f;
    float y = rp.y * (float)Wl + of.y - 0.5f;
    float xf = floorf(x), yf = floorf(y);
    float fx = x - xf, fy = y - yf;
    int ix = (int)xf, iy = (int)yf;

    int ixb = min(max(ix, 0), Wl - 2);
    int iyb = min(max(iy, 0), Wl - 2);
    int col = ixb + half;             // this half's x column
    int r1  = iyb + 1;

    // weight of a given column/row index under zero-padding rules
    float cw  = (col == ix) ? (1.f - fx) : (col == ix + 1) ? fx : 0.f;
    float rw0 = (iyb == iy) ? (1.f - fy) : (iyb == iy + 1) ? fy : 0.f;
    float rw1 = (r1  == iy) ? (1.f - fy) : (r1  == iy + 1) ? fy : 0.f;

    float wcw  = w * cw;
    float wA_s = wcw * rw0;           // tap (col, row iyb)
    float wB_s = wcw * rw1;           // tap (col, row iyb+1)
    unsigned pk_s = (unsigned)(start + iyb * Wl + ixb)
                  | ((unsigned)(start + r1 * Wl + ixb) << 16);

    // ---- gather loop ----
    const int h16 = lane & 16;
    // base includes half*16 (selects colB = pos+1) and channel pair pt
    const __half2* vl = (const __half2*)g_vcache
        + (size_t)(b * NH + h) * TOTV * 16 + h16 + pt;

    float acc0 = 0.f, acc1 = 0.f;
#pragma unroll
    for (int i = 0; i < 16; i++) {
        unsigned pk = __shfl_sync(0xffffffffu, pk_s, i | h16);
        float wA    = __shfl_sync(0xffffffffu, wA_s, i | h16);
        float wB    = __shfl_sync(0xffffffffu, wB_s, i | h16);
        float2 v0 = __half22float2(__ldg(vl + (pk & 0xFFFFu) * 16));
        float2 v1 = __half22float2(__ldg(vl + (pk >> 16) * 16));
        acc0 += wA * v0.x + wB * v1.x;
        acc1 += wA * v0.y + wB * v1.y;
    }
    // combine colA (half 0) and colB (half 1) partial sums
    acc0 += __shfl_xor_sync(0xffffffffu, acc0, 16);
    acc1 += __shfl_xor_sync(0xffffffffu, acc1, 16);

    // ---- smem transpose for coalesced [b, C, q] stores ----
    __shared__ float sm[32][33];
    if (half == 0) {
        sm[2 * pt][warp]     = acc0;
        sm[2 * pt + 1][warp] = acc1;
    }
    __syncthreads();
    out[((size_t)(b * 256 + h * 32 + warp)) * NQ + blockIdx.x * 32 + lane] =
        sm[warp][lane];
}

// ---------------------------------------------------------------------------
// Launch
// ---------------------------------------------------------------------------
extern "C" void kernel_launch(void* const* d_in, const int* in_sizes, int n_in,
                              void* d_out, int out_size) {
    const float* query = (const float*)d_in[0];
    const float* value = (const float*)d_in[1];
    const float* refp  = (const float*)d_in[2];
    const float* Woff  = (const float*)d_in[3];
    const float* boff  = (const float*)d_in[4];
    const float* Wattn = (const float*)d_in[5];
    const float* battn = (const float*)d_in[6];
    float* out = (float*)d_out;

    gemm_conv_kernel<<<GEMM_BLOCKS + CONV_BLOCKS, 256>>>(
        query, value, Woff, Wattn, boff, battn);

    dim3 mgrid(NQ / 32, NH, BS);                 // (512, 8, 2)
    msda_kernel<<<mgrid, 1024>>>(refp, out);
}

// round 4
// speedup vs baseline: 1.3727x; 1.3727x over previous
#include <cuda_runtime.h>
#include <cuda_fp16.h>
#include <cstdint>
#include <math.h>

// ---------------------------------------------------------------------------
// Problem constants
// ---------------------------------------------------------------------------
#define BS   2
#define NQ   16384
#define E    256
#define NH   8
#define NL   4
#define NP   4
#define TOTV 21760         // total spatial positions across levels
#define NOUT 384           // 256 offsets + 128 attn logits per query
#define M_TOT (BS * NQ)    // 32768
#define CONV_ITEMS (BS * TOTV * NH * 8)   // float4 items: 2,785,280
#define GRID_FUSED 1024    // 768 gemm + 256 conv (every 4th block)

// Scratch for GEMM output: [32768, 384] f32
__device__ float g_scratch[(size_t)M_TOT * NOUT];
// fp16 value cache, transposed: [b][h][pos][32ch]
__device__ __align__(128) __half g_vcache[(size_t)BS * NH * TOTV * 32];

// ---------------------------------------------------------------------------
// fp16 mma m16n8k16, f32 accumulate
// ---------------------------------------------------------------------------
__device__ __forceinline__ void mma_f16(float c[4], const unsigned a[4],
                                        unsigned b0, unsigned b1) {
    asm volatile(
        "mma.sync.aligned.m16n8k16.row.col.f32.f16.f16.f32 "
        "{%0,%1,%2,%3}, {%4,%5,%6,%7}, {%8,%9}, {%0,%1,%2,%3};"
        : "+f"(c[0]), "+f"(c[1]), "+f"(c[2]), "+f"(c[3])
        : "r"(a[0]), "r"(a[1]), "r"(a[2]), "r"(a[3]), "r"(b0), "r"(b1));
}

// ---------------------------------------------------------------------------
// Fused kernel. Block roles interleaved so conv overlaps with GEMM compute:
//   blockIdx % 4 == 3  -> conv (256 fat grid-stride blocks, value -> fp16
//                         transposed cache [b][h][pos][32ch])
//   else               -> GEMM block (768 of them)
// GEMM: C[m,n] = sum_k Q[m,k]*Wc[n,k] + bias[n], fp16 inputs, f32 accum.
// Block tile BM=128, BN=128, BK=32; 8 warps (4m x 2n), warp tile 32x64.
// ---------------------------------------------------------------------------
__global__ __launch_bounds__(256) void gemm_conv_kernel(
    const float* __restrict__ Q,
    const float* __restrict__ value,
    const float* __restrict__ Woff,
    const float* __restrict__ Wattn,
    const float* __restrict__ boff,
    const float* __restrict__ battn)
{
    if ((blockIdx.x & 3) == 3) {
        // ---- conv: value -> fp16 transposed cache, grid-stride ----
        int cb = blockIdx.x >> 2;                    // 0..255
        for (int t = cb * 256 + threadIdx.x; t < CONV_ITEMS; t += 256 * 256) {
            int c4 = t & 7;                          // 4-channel group
            int h  = (t >> 3) & 7;
            int pb = t >> 6;                         // b*TOTV + pos
            int b  = (pb >= TOTV) ? 1 : 0;
            int pos = pb - b * TOTV;
            float4 v = *(const float4*)(value + ((size_t)pb * 8 + h) * 32 + c4 * 4);
            __half2 h01 = __floats2half2_rn(v.x, v.y);
            __half2 h23 = __floats2half2_rn(v.z, v.w);
            uint2 pk;
            pk.x = *(const unsigned*)&h01;
            pk.y = *(const unsigned*)&h23;
            ((uint2*)g_vcache)[((size_t)(b * 8 + h) * TOTV + pos) * 8 + c4] = pk;
        }
        return;
    }

    // ---- GEMM ----
    __shared__ __half As[128][40];
    __shared__ __half Bs[128][40];

    const int tid  = threadIdx.x;
    const int bid  = (blockIdx.x >> 2) * 3 + (blockIdx.x & 3);  // 0..767
    const int mblk = bid & 255;
    const int nblk = bid >> 8;
    const int m0   = mblk * 128;
    const int n0   = nblk * 128;
    const int warp = tid >> 5, lane = tid & 31;
    const int wm   = (warp & 3) * 32;
    const int wn   = (warp >> 2) * 64;
    const int g    = lane >> 2;
    const int tg   = lane & 3;

    const float* Bbase = (nblk == 2) ? Wattn : (Woff + (size_t)n0 * 256);

    float acc[2][8][4];
#pragma unroll
    for (int mi = 0; mi < 2; mi++)
#pragma unroll
        for (int ni = 0; ni < 8; ni++)
#pragma unroll
            for (int k = 0; k < 4; k++) acc[mi][ni][k] = 0.f;

    float4 aS[4], bS[4];
#pragma unroll
    for (int i = 0; i < 4; i++) {
        int idx = tid + i * 256;
        int r = idx >> 3, c = (idx & 7) * 4;
        aS[i] = *(const float4*)(Q + (size_t)(m0 + r) * 256 + c);
        bS[i] = *(const float4*)(Bbase + (size_t)r * 256 + c);
    }

#pragma unroll
    for (int kt = 0; kt < 8; kt++) {
        if (kt) __syncthreads();
        // stage registers -> smem as fp16 (STS.64 per float4)
#pragma unroll
        for (int i = 0; i < 4; i++) {
            int idx = tid + i * 256;
            int r = idx >> 3, c = (idx & 7) * 4;
            __half2 a01 = __floats2half2_rn(aS[i].x, aS[i].y);
            __half2 a23 = __floats2half2_rn(aS[i].z, aS[i].w);
            __half2 b01 = __floats2half2_rn(bS[i].x, bS[i].y);
            __half2 b23 = __floats2half2_rn(bS[i].z, bS[i].w);
            uint2 pa; pa.x = *(const unsigned*)&a01; pa.y = *(const unsigned*)&a23;
            uint2 pb; pb.x = *(const unsigned*)&b01; pb.y = *(const unsigned*)&b23;
            *(uint2*)(&As[r][c]) = pa;
            *(uint2*)(&Bs[r][c]) = pb;
        }
        __syncthreads();
        // prefetch next k-tile
        if (kt < 7) {
            int koff = (kt + 1) * 32;
#pragma unroll
            for (int i = 0; i < 4; i++) {
                int idx = tid + i * 256;
                int r = idx >> 3, c = (idx & 7) * 4;
                aS[i] = *(const float4*)(Q + (size_t)(m0 + r) * 256 + koff + c);
                bS[i] = *(const float4*)(Bbase + (size_t)r * 256 + koff + c);
            }
        }
        // compute: 2 k16 steps per 32-wide tile
#pragma unroll
        for (int ks = 0; ks < 32; ks += 16) {
            unsigned a[2][4];
#pragma unroll
            for (int mi = 0; mi < 2; mi++) {
                int r = wm + mi * 16 + g;
                a[mi][0] = *(const unsigned*)(&As[r][ks + 2 * tg]);
                a[mi][1] = *(const unsigned*)(&As[r + 8][ks + 2 * tg]);
                a[mi][2] = *(const unsigned*)(&As[r][ks + 2 * tg + 8]);
                a[mi][3] = *(const unsigned*)(&As[r + 8][ks + 2 * tg + 8]);
            }
#pragma unroll
            for (int ni = 0; ni < 8; ni++) {
                unsigned b0 = *(const unsigned*)(&Bs[wn + ni * 8 + g][ks + 2 * tg]);
                unsigned b1 = *(const unsigned*)(&Bs[wn + ni * 8 + g][ks + 2 * tg + 8]);
                mma_f16(acc[0][ni], a[0], b0, b1);
                mma_f16(acc[1][ni], a[1], b0, b1);
            }
        }
    }

    // Epilogue: add bias (f32), write to scratch
#pragma unroll
    for (int mi = 0; mi < 2; mi++) {
        int row = m0 + wm + mi * 16 + g;
#pragma unroll
        for (int ni = 0; ni < 8; ni++) {
            int col = n0 + wn + ni * 8 + 2 * tg;
            float b0v = (col < 256) ? boff[col] : battn[col - 256];
            float b1v = (col + 1 < 256) ? boff[col + 1] : battn[col + 1 - 256];
            g_scratch[(size_t)row * NOUT + col]           = acc[mi][ni][0] + b0v;
            g_scratch[(size_t)row * NOUT + col + 1]       = acc[mi][ni][1] + b1v;
            g_scratch[(size_t)(row + 8) * NOUT + col]     = acc[mi][ni][2] + b0v;
            g_scratch[(size_t)(row + 8) * NOUT + col + 1] = acc[mi][ni][3] + b1v;
        }
    }
}

// ---------------------------------------------------------------------------
// MSDA kernel: softmax + 16-point bilinear gather + weighted sum.
// One warp per query. fp16 cache layout [b][h][pos][32ch]: the two x-columns
// of a tap are adjacent positions -> one full-warp LDG.32 covers both columns
// of one row as a single 128B contiguous request (lane = half*16 + chpair).
// Validity+bilinear+softmax weights folded per precompute lane.
// ---------------------------------------------------------------------------
__global__ __launch_bounds__(1024) void msda_kernel(
    const float* __restrict__ refp,
    float* __restrict__ out)
{
    const int b    = blockIdx.z;
    const int h    = blockIdx.y;
    const int warp = threadIdx.x >> 5;
    const int lane = threadIdx.x & 31;
    const int q    = blockIdx.x * 32 + warp;
    const int qg   = b * NQ + q;

    const float* sc = g_scratch + (size_t)qg * NOUT;

    const int pt   = lane & 15;       // point index (precompute in both halves)
    const int half = lane >> 4;       // 0 -> colA (x0), 1 -> colB (x1)
    const int l    = pt >> 2;
    const int p    = pt & 3;
    const int Wl   = 128 >> l;
    const int start = (l == 0) ? 0 : (l == 1) ? 16384 : (l == 2) ? 20480 : 21504;

    // ---- softmax over the 16 logits (replicated in both halves) ----
    float lg = sc[256 + h * 16 + pt];
    float mx = lg;
#pragma unroll
    for (int o = 8; o; o >>= 1)
        mx = fmaxf(mx, __shfl_xor_sync(0xffffffffu, mx, o));
    float e = __expf(lg - mx);
    float s = e;
#pragma unroll
    for (int o = 8; o; o >>= 1)
        s += __shfl_xor_sync(0xffffffffu, s, o);
    float w = e / s;

    // ---- per-point sampling position, clamped base + folded weights ----
    float2 of = ((const float2*)(sc + h * 32))[pt];
    float2 rp = ((const float2*)(refp + (size_t)qg * 8))[p];

    float x = rp.x * (float)Wl + of.x - 0.5f;
    float y = rp.y * (float)Wl + of.y - 0.5f;
    float xf = floorf(x), yf = floorf(y);
    float fx = x - xf, fy = y - yf;
    int ix = (int)xf, iy = (int)yf;

    int ixb = min(max(ix, 0), Wl - 2);
    int iyb = min(max(iy, 0), Wl - 2);
    int col = ixb + half;             // this half's x column
    int r1  = iyb + 1;

    // weight of a given column/row index under zero-padding rules
    float cw  = (col == ix) ? (1.f - fx) : (col == ix + 1) ? fx : 0.f;
    float rw0 = (iyb == iy) ? (1.f - fy) : (iyb == iy + 1) ? fy : 0.f;
    float rw1 = (r1  == iy) ? (1.f - fy) : (r1  == iy + 1) ? fy : 0.f;

    float wcw  = w * cw;
    float wA_s = wcw * rw0;           // tap (col, row iyb)
    float wB_s = wcw * rw1;           // tap (col, row iyb+1)
    unsigned pk_s = (unsigned)(start + iyb * Wl + ixb)
                  | ((unsigned)(start + r1 * Wl + ixb) << 16);

    // ---- gather loop ----
    const int h16 = lane & 16;
    // base includes half*16 (selects colB = pos+1) and channel pair pt
    const __half2* vl = (const __half2*)g_vcache
        + (size_t)(b * NH + h) * TOTV * 16 + h16 + pt;

    float acc0 = 0.f, acc1 = 0.f;
#pragma unroll
    for (int i = 0; i < 16; i++) {
        unsigned pk = __shfl_sync(0xffffffffu, pk_s, i | h16);
        float wA    = __shfl_sync(0xffffffffu, wA_s, i | h16);
        float wB    = __shfl_sync(0xffffffffu, wB_s, i | h16);
        float2 v0 = __half22float2(__ldg(vl + (pk & 0xFFFFu) * 16));
        float2 v1 = __half22float2(__ldg(vl + (pk >> 16) * 16));
        acc0 += wA * v0.x + wB * v1.x;
        acc1 += wA * v0.y + wB * v1.y;
    }
    // combine colA (half 0) and colB (half 1) partial sums
    acc0 += __shfl_xor_sync(0xffffffffu, acc0, 16);
    acc1 += __shfl_xor_sync(0xffffffffu, acc1, 16);

    // ---- smem transpose for coalesced [b, C, q] stores ----
    __shared__ float sm[32][33];
    if (half == 0) {
        sm[2 * pt][warp]     = acc0;
        sm[2 * pt + 1][warp] = acc1;
    }
    __syncthreads();
    out[((size_t)(b * 256 + h * 32 + warp)) * NQ + blockIdx.x * 32 + lane] =
        sm[warp][lane];
}

// ---------------------------------------------------------------------------
// Launch
// ---------------------------------------------------------------------------
extern "C" void kernel_launch(void* const* d_in, const int* in_sizes, int n_in,
                              void* d_out, int out_size) {
    const float* query = (const float*)d_in[0];
    const float* value = (const float*)d_in[1];
    const float* refp  = (const float*)d_in[2];
    const float* Woff  = (const float*)d_in[3];
    const float* boff  = (const float*)d_in[4];
    const float* Wattn = (const float*)d_in[5];
    const float* battn = (const float*)d_in[6];
    float* out = (float*)d_out;

    gemm_conv_kernel<<<GRID_FUSED, 256>>>(
        query, value, Woff, Wattn, boff, battn);

    dim3 mgrid(NQ / 32, NH, BS);                 // (512, 8, 2)
    msda_kernel<<<mgrid, 1024>>>(refp, out);
}

// round 5
// speedup vs baseline: 1.7166x; 1.2505x over previous
#include <cuda_runtime.h>
#include <cuda_fp16.h>
#include <cstdint>
#include <math.h>

// ---------------------------------------------------------------------------
// Problem constants
// ---------------------------------------------------------------------------
#define BS   2
#define NQ   16384
#define E    256
#define NH   8
#define NL   4
#define NP   4
#define TOTV 21760
#define NOUT 384
#define M_TOT (BS * NQ)

#define V_ITEMS (BS * TOTV * NH * 8)      // 2,785,280 float4 items
#define Q_ITEMS (M_TOT * E / 4)           // 2,097,152
#define W_ITEMS (384 * 256 / 4)           // 24,576
#define CONV_TOTAL (V_ITEMS + Q_ITEMS + W_ITEMS)
#define CONV_THREADS (640 * 256)

// GEMM scratch [32768][384] f32
__device__ float g_scratch[(size_t)M_TOT * NOUT];
// fp16 value cache, transposed: [b][h][pos][32ch]
__device__ __align__(128) __half g_vcache[(size_t)BS * NH * TOTV * 32];
// fp16 copies of Q and W (W rows 0-255 = W_off, 256-383 = W_attn)
__device__ __align__(128) __half g_qh[(size_t)M_TOT * E];
__device__ __align__(128) __half g_wh[(size_t)384 * 256];

// ---------------------------------------------------------------------------
// helpers
// ---------------------------------------------------------------------------
__device__ __forceinline__ void mma_f16(float c[4], const unsigned a[4],
                                        unsigned b0, unsigned b1) {
    asm volatile(
        "mma.sync.aligned.m16n8k16.row.col.f32.f16.f16.f32 "
        "{%0,%1,%2,%3}, {%4,%5,%6,%7}, {%8,%9}, {%0,%1,%2,%3};"
        : "+f"(c[0]), "+f"(c[1]), "+f"(c[2]), "+f"(c[3])
        : "r"(a[0]), "r"(a[1]), "r"(a[2]), "r"(a[3]), "r"(b0), "r"(b1));
}

__device__ __forceinline__ void cp16(void* smem, const void* gmem) {
    unsigned s = (unsigned)__cvta_generic_to_shared(smem);
    asm volatile("cp.async.ca.shared.global [%0], [%1], 16;\n"
                 :: "r"(s), "l"(gmem));
}
#define CP_COMMIT() asm volatile("cp.async.commit_group;\n")
#define CP_WAIT(n)  asm volatile("cp.async.wait_group %0;\n" :: "n"(n))

__device__ __forceinline__ uint2 f4_to_h4(float4 v) {
    __half2 h01 = __floats2half2_rn(v.x, v.y);
    __half2 h23 = __floats2half2_rn(v.z, v.w);
    uint2 r;
    r.x = *(const unsigned*)&h01;
    r.y = *(const unsigned*)&h23;
    return r;
}

// ---------------------------------------------------------------------------
// Convert kernel: value -> transposed fp16 cache; Q -> fp16; W -> fp16.
// Pure streaming, grid-stride; 640 blocks x 256 threads.
// ---------------------------------------------------------------------------
__global__ __launch_bounds__(256) void convert_kernel(
    const float* __restrict__ value,
    const float* __restrict__ Q,
    const float* __restrict__ Woff,
    const float* __restrict__ Wattn)
{
    for (int t = blockIdx.x * 256 + threadIdx.x; t < CONV_TOTAL;
         t += CONV_THREADS) {
        if (t < V_ITEMS) {
            // value[b][pos][h][32ch] -> vcache[b][h][pos][32ch]
            int c4 = t & 7;
            int h  = (t >> 3) & 7;
            int pb = t >> 6;                 // b*TOTV + pos
            int b  = (pb >= TOTV) ? 1 : 0;
            int pos = pb - b * TOTV;
            float4 v = *(const float4*)(value + ((size_t)pb * 8 + h) * 32 + c4 * 4);
            ((uint2*)g_vcache)[((size_t)(b * 8 + h) * TOTV + pos) * 8 + c4] =
                f4_to_h4(v);
        } else if (t < V_ITEMS + Q_ITEMS) {
            int i = t - V_ITEMS;
            ((uint2*)g_qh)[i] = f4_to_h4(((const float4*)Q)[i]);
        } else {
            int i = t - V_ITEMS - Q_ITEMS;   // 0..24575
            float4 v = (i < 16384) ? ((const float4*)Woff)[i]
                                   : ((const float4*)Wattn)[i - 16384];
            ((uint2*)g_wh)[i] = f4_to_h4(v);
        }
    }
}

// ---------------------------------------------------------------------------
// GEMM: C[m,n] = sum_k Qh[m,k]*Wh[n,k] + bias[n], fp16 in, f32 accum.
// BM=128, BN=128, BK=32; cp.async 2-stage double buffer; 8 warps (4m x 2n).
// grid = (256, 3)
// ---------------------------------------------------------------------------
__global__ __launch_bounds__(256) void gemm_kernel(
    const float* __restrict__ boff,
    const float* __restrict__ battn)
{
    __shared__ __half As[2][128][40];
    __shared__ __half Bs[2][128][40];

    const int tid  = threadIdx.x;
    const int m0   = blockIdx.x * 128;
    const int n0   = blockIdx.y * 128;
    const int warp = tid >> 5, lane = tid & 31;
    const int wm   = (warp & 3) * 32;
    const int wn   = (warp >> 2) * 64;
    const int g    = lane >> 2;
    const int tg   = lane & 3;

    // staging coords: 512 16B-chunks per tile, 2 per thread
    const int r0 = tid >> 2, c0 = (tid & 3) * 8;          // chunk tid
    const int r1 = (tid + 256) >> 2, c1 = c0;             // chunk tid+256

    float acc[2][8][4];
#pragma unroll
    for (int mi = 0; mi < 2; mi++)
#pragma unroll
        for (int ni = 0; ni < 8; ni++)
#pragma unroll
            for (int k = 0; k < 4; k++) acc[mi][ni][k] = 0.f;

    const __half* Abase = g_qh + (size_t)m0 * 256;
    const __half* Bbase = g_wh + (size_t)n0 * 256;

    // prologue: stage 0
    cp16(&As[0][r0][c0], Abase + r0 * 256 + c0);
    cp16(&As[0][r1][c1], Abase + r1 * 256 + c1);
    cp16(&Bs[0][r0][c0], Bbase + r0 * 256 + c0);
    cp16(&Bs[0][r1][c1], Bbase + r1 * 256 + c1);
    CP_COMMIT();

#pragma unroll
    for (int kt = 0; kt < 8; kt++) {
        if (kt < 7) {
            int s = (kt + 1) & 1, ko = (kt + 1) * 32;
            cp16(&As[s][r0][c0], Abase + r0 * 256 + ko + c0);
            cp16(&As[s][r1][c1], Abase + r1 * 256 + ko + c1);
            cp16(&Bs[s][r0][c0], Bbase + r0 * 256 + ko + c0);
            cp16(&Bs[s][r1][c1], Bbase + r1 * 256 + ko + c1);
            CP_COMMIT();
            CP_WAIT(1);
        } else {
            CP_WAIT(0);
        }
        __syncthreads();
        const int s = kt & 1;
#pragma unroll
        for (int ks = 0; ks < 32; ks += 16) {
            unsigned a[2][4];
#pragma unroll
            for (int mi = 0; mi < 2; mi++) {
                int r = wm + mi * 16 + g;
                a[mi][0] = *(const unsigned*)(&As[s][r][ks + 2 * tg]);
                a[mi][1] = *(const unsigned*)(&As[s][r + 8][ks + 2 * tg]);
                a[mi][2] = *(const unsigned*)(&As[s][r][ks + 2 * tg + 8]);
                a[mi][3] = *(const unsigned*)(&As[s][r + 8][ks + 2 * tg + 8]);
            }
#pragma unroll
            for (int ni = 0; ni < 8; ni++) {
                unsigned b0 = *(const unsigned*)(&Bs[s][wn + ni * 8 + g][ks + 2 * tg]);
                unsigned b1 = *(const unsigned*)(&Bs[s][wn + ni * 8 + g][ks + 2 * tg + 8]);
                mma_f16(acc[0][ni], a[0], b0, b1);
                mma_f16(acc[1][ni], a[1], b0, b1);
            }
        }
        __syncthreads();
    }

    // epilogue: bias + store f32
#pragma unroll
    for (int mi = 0; mi < 2; mi++) {
        int row = m0 + wm + mi * 16 + g;
#pragma unroll
        for (int ni = 0; ni < 8; ni++) {
            int col = n0 + wn + ni * 8 + 2 * tg;
            float b0v = (col < 256) ? boff[col] : battn[col - 256];
            float b1v = (col + 1 < 256) ? boff[col + 1] : battn[col + 1 - 256];
            g_scratch[(size_t)row * NOUT + col]           = acc[mi][ni][0] + b0v;
            g_scratch[(size_t)row * NOUT + col + 1]       = acc[mi][ni][1] + b1v;
            g_scratch[(size_t)(row + 8) * NOUT + col]     = acc[mi][ni][2] + b0v;
            g_scratch[(size_t)(row + 8) * NOUT + col + 1] = acc[mi][ni][3] + b1v;
        }
    }
}

// ---------------------------------------------------------------------------
// MSDA kernel. One warp per (b,h,query). Preamble: lanes 0-15 compute point
// pt's clamped tap base offsets + 4 folded weights, stored as two 8B records
// (one per row) in smem. Gather loop (16 iters): LDS.64 broadcast record,
// one LDG.64 covers this lane's (row, col, 4 channels) tap; 4 scalar FFMA.
// Lane map: row = lane>>4, col = (lane>>3)&1, 4-ch group = lane&7.
// ---------------------------------------------------------------------------
__global__ __launch_bounds__(1024) void msda_kernel(
    const float* __restrict__ refp,
    float* __restrict__ out)
{
    const int b    = blockIdx.z;
    const int h    = blockIdx.y;
    const int warp = threadIdx.x >> 5;
    const int lane = threadIdx.x & 31;
    const int q    = blockIdx.x * 32 + warp;
    const int qg   = b * NQ + q;

    const float* sc = g_scratch + (size_t)qg * NOUT;

    const int pt = lane & 15;
    const int l  = pt >> 2;
    const int p  = pt & 3;
    const int Wl = 128 >> l;
    const int start = (l == 0) ? 0 : (l == 1) ? 16384 : (l == 2) ? 20480 : 21504;

    // ---- softmax over 16 logits (mirrored in both halves) ----
    float lg = sc[256 + h * 16 + pt];
    float mx = lg;
#pragma unroll
    for (int o = 8; o; o >>= 1)
        mx = fmaxf(mx, __shfl_xor_sync(0xffffffffu, mx, o));
    float e = __expf(lg - mx);
    float s = e;
#pragma unroll
    for (int o = 8; o; o >>= 1)
        s += __shfl_xor_sync(0xffffffffu, s, o);
    float w = e / s;

    // ---- per-point tap geometry + folded weights ----
    float2 of = ((const float2*)(sc + h * 32))[pt];
    float2 rp = ((const float2*)(refp + (size_t)qg * 8))[p];

    float x = rp.x * (float)Wl + of.x - 0.5f;
    float y = rp.y * (float)Wl + of.y - 0.5f;
    float xf = floorf(x), yf = floorf(y);
    float fx = x - xf, fy = y - yf;
    int ix = (int)xf, iy = (int)yf;
    int ixb = min(max(ix, 0), Wl - 2);
    int iyb = min(max(iy, 0), Wl - 2);

    float cw0 = (ixb == ix) ? (1.f - fx) : (ixb == ix + 1) ? fx : 0.f;
    float cw1 = (ixb + 1 == ix) ? (1.f - fx) : (ixb + 1 == ix + 1) ? fx : 0.f;
    float rw0 = (iyb == iy) ? (1.f - fy) : (iyb == iy + 1) ? fy : 0.f;
    float rw1 = (iyb + 1 == iy) ? (1.f - fy) : (iyb + 1 == iy + 1) ? fy : 0.f;

    float wr0 = w * rw0, wr1 = w * rw1;
    __half2 h0 = __floats2half2_rn(wr0 * cw0, wr0 * cw1);   // row0: col0,col1
    __half2 h1 = __floats2half2_rn(wr1 * cw0, wr1 * cw1);   // row1
    unsigned offA = (unsigned)(start + iyb * Wl + ixb) * 64u;
    unsigned offB = offA + (unsigned)Wl * 64u;

    // ---- smem records: rec[warp][row][pt], stride 17 (bank padding) ----
    __shared__ uint2 rec[32][2][17];
    if (lane < 16) {
        uint2 r0; r0.x = offA; r0.y = *(const unsigned*)&h0;
        uint2 r1; r1.x = offB; r1.y = *(const unsigned*)&h1;
        rec[warp][0][pt] = r0;
        rec[warp][1][pt] = r1;
    }
    __syncwarp();

    // ---- gather: lane = (row = lane>>4, col = bit3, ch4 = lane&7) ----
    const int row    = lane >> 4;
    const int shamt  = ((lane >> 3) & 1) * 16;
    const uint2* recp = &rec[warp][row][0];
    // (lane&15)*8 folds col (+64B) and channel group (+8B each)
    const char* vbase = (const char*)g_vcache
        + (size_t)(b * NH + h) * TOTV * 64 + (lane & 15) * 8;

    float a0 = 0.f, a1 = 0.f, a2 = 0.f, a3 = 0.f;
#pragma unroll
    for (int i = 0; i < 16; i++) {
        uint2 ei = recp[i];                               // LDS.64 broadcast
        uint2 v  = __ldg((const uint2*)(vbase + ei.x));   // LDG.64: 4 channels
        float wt = __half2float(
            __ushort_as_half((unsigned short)(ei.y >> shamt)));
        float2 f0 = __half22float2(*(const __half2*)&v.x);
        float2 f1 = __half22float2(*(const __half2*)&v.y);
        a0 += wt * f0.x; a1 += wt * f0.y;
        a2 += wt * f1.x; a3 += wt * f1.y;
    }
    // reduce over col (xor 8) then row (xor 16)
#pragma unroll
    for (int o = 8; o <= 16; o <<= 1) {
        a0 += __shfl_xor_sync(0xffffffffu, a0, o);
        a1 += __shfl_xor_sync(0xffffffffu, a1, o);
        a2 += __shfl_xor_sync(0xffffffffu, a2, o);
        a3 += __shfl_xor_sync(0xffffffffu, a3, o);
    }

    // ---- smem transpose for coalesced [b, C, q] stores ----
    __shared__ float sm[32][33];
    if (lane < 8) {
        sm[lane * 4 + 0][warp] = a0;
        sm[lane * 4 + 1][warp] = a1;
        sm[lane * 4 + 2][warp] = a2;
        sm[lane * 4 + 3][warp] = a3;
    }
    __syncthreads();
    out[((size_t)(b * 256 + h * 32 + warp)) * NQ + blockIdx.x * 32 + lane] =
        sm[warp][lane];
}

// ---------------------------------------------------------------------------
// Launch
// ---------------------------------------------------------------------------
extern "C" void kernel_launch(void* const* d_in, const int* in_sizes, int n_in,
                              void* d_out, int out_size) {
    const float* query = (const float*)d_in[0];
    const float* value = (const float*)d_in[1];
    const float* refp  = (const float*)d_in[2];
    const float* Woff  = (const float*)d_in[3];
    const float* boff  = (const float*)d_in[4];
    const float* Wattn = (const float*)d_in[5];
    const float* battn = (const float*)d_in[6];
    float* out = (float*)d_out;

    convert_kernel<<<640, 256>>>(value, query, Woff, Wattn);

    dim3 ggrid(M_TOT / 128, 3);
    gemm_kernel<<<ggrid, 256>>>(boff, battn);

    dim3 mgrid(NQ / 32, NH, BS);
    msda_kernel<<<mgrid, 1024>>>(refp, out);
}

// round 7
// speedup vs baseline: 2.0242x; 1.1791x over previous
#include <cuda_runtime.h>
#include <cuda_fp16.h>
#include <cstdint>
#include <math.h>

// ---------------------------------------------------------------------------
// Problem constants
// ---------------------------------------------------------------------------
#define BS   2
#define NQ   16384
#define E    256
#define NH   8
#define NL   4
#define NP   4
#define TOTV 21760
#define NOUT 384
#define M_TOT (BS * NQ)

// convert quads (each thread processes 4 float4 = 64B in, 32B out)
#define V_QUADS (BS * TOTV * NH * 2)      // 696,320
#define Q_QUADS (M_TOT * E / 16)          // 524,288
#define W_QUADS (384 * 256 / 16)          // 6,144
#define CONV_QUADS (V_QUADS + Q_QUADS + W_QUADS)   // 1,226,752
#define CONV_GRID  (CONV_QUADS / 256)     // 4792

// GEMM scratch [32768][384] f32
__device__ float g_scratch[(size_t)M_TOT * NOUT];
// fp16 value cache, transposed: [b][h][pos][32ch]
__device__ __align__(128) __half g_vcache[(size_t)BS * NH * TOTV * 32];
// fp16 copies of Q and W (W rows 0-255 = W_off, 256-383 = W_attn)
__device__ __align__(128) __half g_qh[(size_t)M_TOT * E];
__device__ __align__(128) __half g_wh[(size_t)384 * 256];

// ---------------------------------------------------------------------------
// helpers
// ---------------------------------------------------------------------------
__device__ __forceinline__ void mma_f16(float c[4], const unsigned a[4],
                                        unsigned b0, unsigned b1) {
    asm volatile(
        "mma.sync.aligned.m16n8k16.row.col.f32.f16.f16.f32 "
        "{%0,%1,%2,%3}, {%4,%5,%6,%7}, {%8,%9}, {%0,%1,%2,%3};"
        : "+f"(c[0]), "+f"(c[1]), "+f"(c[2]), "+f"(c[3])
        : "r"(a[0]), "r"(a[1]), "r"(a[2]), "r"(a[3]), "r"(b0), "r"(b1));
}

__device__ __forceinline__ void cp16(void* smem, const void* gmem) {
    unsigned s = (unsigned)__cvta_generic_to_shared(smem);
    asm volatile("cp.async.ca.shared.global [%0], [%1], 16;\n"
                 :: "r"(s), "l"(gmem));
}
#define CP_COMMIT() asm volatile("cp.async.commit_group;\n")
#define CP_WAIT(n)  asm volatile("cp.async.wait_group %0;\n" :: "n"(n))

__device__ __forceinline__ unsigned f2_to_h2(float a, float b) {
    __half2 h = __floats2half2_rn(a, b);
    return *(const unsigned*)&h;
}

// ---------------------------------------------------------------------------
// Convert kernel: value -> transposed fp16 cache; Q -> fp16; W -> fp16.
// Each thread handles 4 consecutive float4 items (64B load, 32B store, MLP=4).
// grid = 4792 x 256, exact cover.
// ---------------------------------------------------------------------------
__global__ __launch_bounds__(256) void convert_kernel(
    const float* __restrict__ value,
    const float* __restrict__ Q,
    const float* __restrict__ Woff,
    const float* __restrict__ Wattn)
{
    int T = blockIdx.x * 256 + threadIdx.x;
    float4 v[4];
    uint4* dst;
    if (T < V_QUADS) {
        // items 4T..4T+3: same (b,pos,h), c4 base = (4T)&7 in {0,4}
        int c4b = (4 * T) & 7;
        int h   = (T >> 1) & 7;
        int pb  = T >> 4;                 // b*TOTV + pos
        int b   = (pb >= TOTV) ? 1 : 0;
        int pos = pb - b * TOTV;
        const float4* src = (const float4*)(value
            + ((size_t)pb * 8 + h) * 32 + c4b * 4);
#pragma unroll
        for (int j = 0; j < 4; j++) v[j] = src[j];
        dst = (uint4*)((uint2*)g_vcache
            + ((size_t)(b * 8 + h) * TOTV + pos) * 8 + c4b);
    } else if (T < V_QUADS + Q_QUADS) {
        int i = T - V_QUADS;
        const float4* src = (const float4*)Q + 4 * i;
#pragma unroll
        for (int j = 0; j < 4; j++) v[j] = src[j];
        dst = (uint4*)g_qh + 2 * i;       // 32B per thread (BUGFIX: was + i)
    } else {
        int i = T - V_QUADS - Q_QUADS;    // 0..6143; Woff quads < 4096
        const float4* src = (i < 4096) ? ((const float4*)Woff + 4 * i)
                                       : ((const float4*)Wattn + 4 * (i - 4096));
#pragma unroll
        for (int j = 0; j < 4; j++) v[j] = src[j];
        dst = (uint4*)g_wh + 2 * i;       // (BUGFIX: was + i)
    }
    uint4 o0, o1;
    o0.x = f2_to_h2(v[0].x, v[0].y); o0.y = f2_to_h2(v[0].z, v[0].w);
    o0.z = f2_to_h2(v[1].x, v[1].y); o0.w = f2_to_h2(v[1].z, v[1].w);
    o1.x = f2_to_h2(v[2].x, v[2].y); o1.y = f2_to_h2(v[2].z, v[2].w);
    o1.z = f2_to_h2(v[3].x, v[3].y); o1.w = f2_to_h2(v[3].z, v[3].w);
    dst[0] = o0;
    dst[1] = o1;
}

// ---------------------------------------------------------------------------
// GEMM: C[m,n] = sum_k Qh[m,k]*Wh[n,k] + bias[n], fp16 in, f32 accum.
// BM=128, BN=128, BK=32; cp.async 2-stage double buffer; 8 warps (4m x 2n).
// grid = (256, 3)
// ---------------------------------------------------------------------------
__global__ __launch_bounds__(256) void gemm_kernel(
    const float* __restrict__ boff,
    const float* __restrict__ battn)
{
    __shared__ __half As[2][128][40];
    __shared__ __half Bs[2][128][40];

    const int tid  = threadIdx.x;
    const int m0   = blockIdx.x * 128;
    const int n0   = blockIdx.y * 128;
    const int warp = tid >> 5, lane = tid & 31;
    const int wm   = (warp & 3) * 32;
    const int wn   = (warp >> 2) * 64;
    const int g    = lane >> 2;
    const int tg   = lane & 3;

    const int r0 = tid >> 2, c0 = (tid & 3) * 8;
    const int r1 = (tid + 256) >> 2, c1 = c0;

    float acc[2][8][4];
#pragma unroll
    for (int mi = 0; mi < 2; mi++)
#pragma unroll
        for (int ni = 0; ni < 8; ni++)
#pragma unroll
            for (int k = 0; k < 4; k++) acc[mi][ni][k] = 0.f;

    const __half* Abase = g_qh + (size_t)m0 * 256;
    const __half* Bbase = g_wh + (size_t)n0 * 256;

    cp16(&As[0][r0][c0], Abase + r0 * 256 + c0);
    cp16(&As[0][r1][c1], Abase + r1 * 256 + c1);
    cp16(&Bs[0][r0][c0], Bbase + r0 * 256 + c0);
    cp16(&Bs[0][r1][c1], Bbase + r1 * 256 + c1);
    CP_COMMIT();

#pragma unroll
    for (int kt = 0; kt < 8; kt++) {
        if (kt < 7) {
            int s = (kt + 1) & 1, ko = (kt + 1) * 32;
            cp16(&As[s][r0][c0], Abase + r0 * 256 + ko + c0);
            cp16(&As[s][r1][c1], Abase + r1 * 256 + ko + c1);
            cp16(&Bs[s][r0][c0], Bbase + r0 * 256 + ko + c0);
            cp16(&Bs[s][r1][c1], Bbase + r1 * 256 + ko + c1);
            CP_COMMIT();
            CP_WAIT(1);
        } else {
            CP_WAIT(0);
        }
        __syncthreads();
        const int s = kt & 1;
#pragma unroll
        for (int ks = 0; ks < 32; ks += 16) {
            unsigned a[2][4];
#pragma unroll
            for (int mi = 0; mi < 2; mi++) {
                int r = wm + mi * 16 + g;
                a[mi][0] = *(const unsigned*)(&As[s][r][ks + 2 * tg]);
                a[mi][1] = *(const unsigned*)(&As[s][r + 8][ks + 2 * tg]);
                a[mi][2] = *(const unsigned*)(&As[s][r][ks + 2 * tg + 8]);
                a[mi][3] = *(const unsigned*)(&As[s][r + 8][ks + 2 * tg + 8]);
            }
#pragma unroll
            for (int ni = 0; ni < 8; ni++) {
                unsigned b0 = *(const unsigned*)(&Bs[s][wn + ni * 8 + g][ks + 2 * tg]);
                unsigned b1 = *(const unsigned*)(&Bs[s][wn + ni * 8 + g][ks + 2 * tg + 8]);
                mma_f16(acc[0][ni], a[0], b0, b1);
                mma_f16(acc[1][ni], a[1], b0, b1);
            }
        }
        __syncthreads();
    }

#pragma unroll
    for (int mi = 0; mi < 2; mi++) {
        int row = m0 + wm + mi * 16 + g;
#pragma unroll
        for (int ni = 0; ni < 8; ni++) {
            int col = n0 + wn + ni * 8 + 2 * tg;
            float b0v = (col < 256) ? boff[col] : battn[col - 256];
            float b1v = (col + 1 < 256) ? boff[col + 1] : battn[col + 1 - 256];
            g_scratch[(size_t)row * NOUT + col]           = acc[mi][ni][0] + b0v;
            g_scratch[(size_t)row * NOUT + col + 1]       = acc[mi][ni][1] + b1v;
            g_scratch[(size_t)(row + 8) * NOUT + col]     = acc[mi][ni][2] + b0v;
            g_scratch[(size_t)(row + 8) * NOUT + col + 1] = acc[mi][ni][3] + b1v;
        }
    }
}

// ---------------------------------------------------------------------------
// MSDA kernel: 2 queries per warp.
// Lane = {qh=bit4, row=bit3, col=bit2, chgroup=bits0-1}. Each 16-lane half
// runs its own query's softmax + tap geometry (shuffle xor<=8 stays in-half),
// writing per-point records (clamped base offset + 2 packed fp16 col-weights
// per row) to smem. Gather loop: 16 iters, point i for BOTH queries; each
// lane does one LDS.64 record + one LDG.128 (8 channels) + 8 FFMA.
// grid = (NQ/64, NH, BS), block = 1024 (32 warps = 64 queries).
// ---------------------------------------------------------------------------
__global__ __launch_bounds__(1024) void msda_kernel(
    const float* __restrict__ refp,
    float* __restrict__ out)
{
    const int b    = blockIdx.z;
    const int h    = blockIdx.y;
    const int warp = threadIdx.x >> 5;
    const int lane = threadIdx.x & 31;
    const int qh   = lane >> 4;
    const int pt   = lane & 15;
    const int q    = blockIdx.x * 64 + warp * 2 + qh;
    const int qg   = b * NQ + q;

    const float* sc = g_scratch + (size_t)qg * NOUT;

    const int l  = pt >> 2;
    const int p  = pt & 3;
    const int Wl = 128 >> l;
    const int start = (l == 0) ? 0 : (l == 1) ? 16384 : (l == 2) ? 20480 : 21504;

    // ---- softmax over 16 logits (within this half's query) ----
    float lg = sc[256 + h * 16 + pt];
    float mx = lg;
#pragma unroll
    for (int o = 8; o; o >>= 1)
        mx = fmaxf(mx, __shfl_xor_sync(0xffffffffu, mx, o));
    float e = __expf(lg - mx);
    float s = e;
#pragma unroll
    for (int o = 8; o; o >>= 1)
        s += __shfl_xor_sync(0xffffffffu, s, o);
    float w = e / s;

    // ---- tap geometry + folded weights for point pt of this query ----
    float2 of = ((const float2*)(sc + h * 32))[pt];
    float2 rp = ((const float2*)(refp + (size_t)qg * 8))[p];

    float x = rp.x * (float)Wl + of.x - 0.5f;
    float y = rp.y * (float)Wl + of.y - 0.5f;
    float xf = floorf(x), yf = floorf(y);
    float fx = x - xf, fy = y - yf;
    int ix = (int)xf, iy = (int)yf;
    int ixb = min(max(ix, 0), Wl - 2);
    int iyb = min(max(iy, 0), Wl - 2);

    float cw0 = (ixb == ix) ? (1.f - fx) : (ixb == ix + 1) ? fx : 0.f;
    float cw1 = (ixb + 1 == ix) ? (1.f - fx) : (ixb + 1 == ix + 1) ? fx : 0.f;
    float rw0 = (iyb == iy) ? (1.f - fy) : (iyb == iy + 1) ? fy : 0.f;
    float rw1 = (iyb + 1 == iy) ? (1.f - fy) : (iyb + 1 == iy + 1) ? fy : 0.f;

    float wr0 = w * rw0, wr1 = w * rw1;
    unsigned w0 = f2_to_h2(wr0 * cw0, wr0 * cw1);   // row0: (col0, col1)
    unsigned w1 = f2_to_h2(wr1 * cw0, wr1 * cw1);   // row1
    unsigned offA = (unsigned)(start + iyb * Wl + ixb) * 64u;
    unsigned offB = offA + (unsigned)Wl * 64u;

    // ---- smem records: rec[warp][qh][row][pt], stride 17 padding ----
    __shared__ uint2 rec[32][2][2][17];
    {
        uint2 r0; r0.x = offA; r0.y = w0;
        uint2 r1; r1.x = offB; r1.y = w1;
        rec[warp][qh][0][pt] = r0;
        rec[warp][qh][1][pt] = r1;
    }
    __syncwarp();

    // ---- gather loop ----
    const int row   = (lane >> 3) & 1;
    const int shamt = ((lane >> 2) & 1) * 16;     // col selects packed weight
    const uint2* recq = &rec[warp][qh][row][0];
    // (lane&7)*16 = col*64B + chgroup*16B
    const char* vbase = (const char*)g_vcache
        + (size_t)(b * NH + h) * TOTV * 64 + (lane & 7) * 16;

    float a0 = 0.f, a1 = 0.f, a2 = 0.f, a3 = 0.f;
    float a4 = 0.f, a5 = 0.f, a6 = 0.f, a7 = 0.f;
#pragma unroll
    for (int i = 0; i < 16; i++) {
        uint2 ei = recq[i];                             // LDS.64 broadcast x4
        uint4 v  = __ldg((const uint4*)(vbase + ei.x)); // 8 channels
        float wt = __half2float(
            __ushort_as_half((unsigned short)(ei.y >> shamt)));
        float2 f0 = __half22float2(*(const __half2*)&v.x);
        float2 f1 = __half22float2(*(const __half2*)&v.y);
        float2 f2 = __half22float2(*(const __half2*)&v.z);
        float2 f3 = __half22float2(*(const __half2*)&v.w);
        a0 += wt * f0.x; a1 += wt * f0.y;
        a2 += wt * f1.x; a3 += wt * f1.y;
        a4 += wt * f2.x; a5 += wt * f2.y;
        a6 += wt * f3.x; a7 += wt * f3.y;
    }
    // reduce over col (xor 4) then row (xor 8); stays within the half
#pragma unroll
    for (int o = 4; o <= 8; o <<= 1) {
        a0 += __shfl_xor_sync(0xffffffffu, a0, o);
        a1 += __shfl_xor_sync(0xffffffffu, a1, o);
        a2 += __shfl_xor_sync(0xffffffffu, a2, o);
        a3 += __shfl_xor_sync(0xffffffffu, a3, o);
        a4 += __shfl_xor_sync(0xffffffffu, a4, o);
        a5 += __shfl_xor_sync(0xffffffffu, a5, o);
        a6 += __shfl_xor_sync(0xffffffffu, a6, o);
        a7 += __shfl_xor_sync(0xffffffffu, a7, o);
    }

    // ---- smem transpose: sm[channel][q_local] ----
    __shared__ float sm[32][68];
    if ((lane & 12) == 0) {                 // lanes 0-3 / 16-19
        int ch = (lane & 3) * 8;
        int qc = warp * 2 + qh;
        sm[ch + 0][qc] = a0; sm[ch + 1][qc] = a1;
        sm[ch + 2][qc] = a2; sm[ch + 3][qc] = a3;
        sm[ch + 4][qc] = a4; sm[ch + 5][qc] = a5;
        sm[ch + 6][qc] = a6; sm[ch + 7][qc] = a7;
    }
    __syncthreads();
    // warp = channel row; lane covers 64 q as float2 -> 512B coalesced
    float2 o2;
    o2.x = sm[warp][lane * 2];
    o2.y = sm[warp][lane * 2 + 1];
    *(float2*)(out + ((size_t)(b * 256 + h * 32 + warp)) * NQ
               + blockIdx.x * 64 + lane * 2) = o2;
}

// ---------------------------------------------------------------------------
// Launch
// ---------------------------------------------------------------------------
extern "C" void kernel_launch(void* const* d_in, const int* in_sizes, int n_in,
                              void* d_out, int out_size) {
    const float* query = (const float*)d_in[0];
    const float* value = (const float*)d_in[1];
    const float* refp  = (const float*)d_in[2];
    const float* Woff  = (const float*)d_in[3];
    const float* boff  = (const float*)d_in[4];
    const float* Wattn = (const float*)d_in[5];
    const float* battn = (const float*)d_in[6];
    float* out = (float*)d_out;

    convert_kernel<<<CONV_GRID, 256>>>(value, query, Woff, Wattn);

    dim3 ggrid(M_TOT / 128, 3);
    gemm_kernel<<<ggrid, 256>>>(boff, battn);

    dim3 mgrid(NQ / 64, NH, BS);
    msda_kernel<<<mgrid, 1024>>>(refp, out);
}